// round 2
// baseline (speedup 1.0000x reference)
#include <cuda_runtime.h>
#include <cstdint>
#include <math.h>

#define T_STEPS 100
#define NPIX    784
#define NOUT    10
#define WPAD    11            /* stride 11 words -> coprime with 32 banks */

// JAX threefry2x32, exact (5 groups of 4 rounds).
__device__ __forceinline__ uint2 tf2x32(uint32_t k0, uint32_t k1,
                                        uint32_t x0, uint32_t x1) {
    uint32_t k2 = k0 ^ k1 ^ 0x1BD11BDAu;
    x0 += k0; x1 += k1;
#define TFR(r) { x0 += x1; x1 = __funnelshift_l(x1, x1, (r)); x1 ^= x0; }
    TFR(13) TFR(15) TFR(26) TFR(6)
    x0 += k1; x1 += k2 + 1u;
    TFR(17) TFR(29) TFR(16) TFR(24)
    x0 += k2; x1 += k0 + 2u;
    TFR(13) TFR(15) TFR(26) TFR(6)
    x0 += k0; x1 += k1 + 3u;
    TFR(17) TFR(29) TFR(16) TFR(24)
    x0 += k1; x1 += k2 + 4u;
    TFR(13) TFR(15) TFR(26) TFR(6)
    x0 += k2; x1 += k0 + 5u;
#undef TFR
    return make_uint2(x0, x1);
}

// smem: keys (100 uint2 = 800B) | Wt (784*11 f32 = 34496B) | xth (8*784 u32 = 25088B)
#define SM_KEYS  0
#define SM_WT    800
#define SM_XTH   (SM_WT + NPIX * WPAD * 4)
#define SM_TOTAL (SM_XTH + 8 * NPIX * 4)

__global__ void __launch_bounds__(256, 2)
snn_kernel(const float* __restrict__ x, const float* __restrict__ W,
           float* __restrict__ out) {
    extern __shared__ unsigned char sm[];
    uint2*    keys = (uint2*)(sm + SM_KEYS);
    float*    Wt   = (float*)(sm + SM_WT);
    uint32_t* xth  = (uint32_t*)(sm + SM_XTH);

    const int tid  = threadIdx.x;
    const int warp = tid >> 5;
    const int lane = tid & 31;
    const int b    = blockIdx.x * 8 + warp;   // 2048 blocks * 8 warps = 16384 batches

    // --- per-timestep keys: jax.random.split(key(42), 100), partitionable
    //     ("foldlike"): key[t] = threefry((0,42), x0=hi(t)=0, x1=lo(t)=t) ---
    if (tid < T_STEPS) {
        uint2 r = tf2x32(0u, 42u, 0u, (uint32_t)tid);
        keys[tid] = r;   // (k1_t, k2_t) = (bits1, bits2)
    }

    // --- transposed, padded weights Wt[p][o] = W[o][p] ---
    for (int i = tid; i < NPIX * NOUT; i += 256) {
        int p = i / NOUT, o = i - p * NOUT;
        Wt[p * WPAD + o] = W[o * NPIX + p];
    }

    // --- integer spike thresholds: u < x  <=>  (bits>>9) < ceil(x * 2^23) ---
    {
        uint32_t* th = xth + warp * NPIX;
        for (int p = lane; p < NPIX; p += 32) {
            double d = (double)x[(size_t)b * NPIX + p] * 8388608.0;
            th[p] = (uint32_t)ceil(d);
        }
    }
    __syncthreads();

    const uint32_t* th  = xth + warp * NPIX;
    const uint32_t base = (uint32_t)b * NPIX;

    float v[NOUT], cnt[NOUT];
#pragma unroll
    for (int o = 0; o < NOUT; o++) { v[o] = 0.f; cnt[o] = 0.f; }

    for (int t = 0; t < T_STEPS; t++) {
        const uint2 kk = keys[t];

        float acc[NOUT];
#pragma unroll
        for (int o = 0; o < NOUT; o++) acc[o] = 0.f;

        for (int p = lane; p < NPIX; p += 32) {
            // partitionable random_bits: counter = uint64 flat index -> (hi=0, lo=i);
            // 32-bit sample = bits1 ^ bits2.
            uint2 r = tf2x32(kk.x, kk.y, 0u, base + (uint32_t)p);
            uint32_t m = (r.x ^ r.y) >> 9;
            bool s = m < th[p];
            const float* wp = Wt + p * WPAD;
#pragma unroll
            for (int o = 0; o < NOUT; o++) {
                float wv = wp[o];
                if (s) acc[o] += wv;
            }
        }

        // butterfly reduce the 10 accumulators (every lane gets totals)
#pragma unroll
        for (int off = 16; off > 0; off >>= 1) {
#pragma unroll
            for (int o = 0; o < NOUT; o++)
                acc[o] += __shfl_xor_sync(0xFFFFFFFFu, acc[o], off);
        }

        // LIF: v += (I - v)/2 ; spike if v>=1 ; hard reset.
        // fmaf == XLA rounding since (I-v)*0.5 is exact (power-of-two scale).
#pragma unroll
        for (int o = 0; o < NOUT; o++) {
            float nv = fmaf(acc[o] - v[o], 0.5f, v[o]);
            if (nv >= 1.0f) { cnt[o] += 1.0f; nv = 0.0f; }
            v[o] = nv;
        }
    }

    if (lane == 0) {
#pragma unroll
        for (int o = 0; o < NOUT; o++)
            out[(size_t)b * NOUT + o] = cnt[o] / 100.0f;
    }
}

extern "C" void kernel_launch(void* const* d_in, const int* in_sizes, int n_in,
                              void* d_out, int out_size) {
    const float* x = (const float*)d_in[0];   // [16384,1,28,28] f32
    const float* W = (const float*)d_in[1];   // [10,784] f32
    float* out = (float*)d_out;               // [16384,10] f32

    cudaFuncSetAttribute(snn_kernel, cudaFuncAttributeMaxDynamicSharedMemorySize,
                         SM_TOTAL);
    snn_kernel<<<2048, 256, SM_TOTAL>>>(x, W, out);
}

// round 3
// speedup vs baseline: 1.1131x; 1.1131x over previous
#include <cuda_runtime.h>
#include <cstdint>
#include <math.h>

#define T_STEPS 100
#define NPIX    784
#define NPAIR   392
#define NOUT    10
#define LSTR    41           /* words per pair group: 4 patterns * 10 + 1 pad */

// Integer add forced onto the FMA pipe (IMAD): d = a*one + b, one==1 at runtime
// but opaque to the compiler so it cannot strength-reduce to IADD3.
__device__ __forceinline__ uint32_t madd(uint32_t a, uint32_t b, uint32_t one) {
    uint32_t d;
    asm("mad.lo.u32 %0, %1, %2, %3;" : "=r"(d) : "r"(a), "r"(one), "r"(b));
    return d;
}

// JAX threefry2x32, exact; x0 initial = 0. Adds go through IMAD (fma pipe),
// rot/xor stay on the ALU pipe -> balanced dual-pipe utilization.
__device__ __forceinline__ uint2 tf2x32(uint32_t k0, uint32_t k1, uint32_t k2,
                                        uint32_t x1in, uint32_t one) {
    uint32_t x0 = k0;                       // 0 + k0
    uint32_t x1 = madd(x1in, k1, one);
#define R(r) { x0 = madd(x0, x1, one); x1 = __funnelshift_l(x1, x1, (r)); x1 ^= x0; }
    R(13) R(15) R(26) R(6)
    x0 = madd(x0, k1, one); x1 = madd(x1, k2 + 1u, one);
    R(17) R(29) R(16) R(24)
    x0 = madd(x0, k2, one); x1 = madd(x1, k0 + 2u, one);
    R(13) R(15) R(26) R(6)
    x0 = madd(x0, k0, one); x1 = madd(x1, k1 + 3u, one);
    R(17) R(29) R(16) R(24)
    x0 = madd(x0, k1, one); x1 = madd(x1, k2 + 4u, one);
    R(13) R(15) R(26) R(6)
    x0 = madd(x0, k2, one); x1 = madd(x1, k0 + 5u, one);
#undef R
    return make_uint2(x0, x1);
}

// smem: keys (100 uint2 = 800B) | pair-LUT (392*41*4 = 64288B) | xth (8*784*4 = 25088B)
#define SM_KEYS  0
#define SM_LUT   800
#define SM_XTH   (SM_LUT + NPAIR * LSTR * 4)
#define SM_TOTAL (SM_XTH + 8 * NPIX * 4)

__global__ void __launch_bounds__(256, 2)
snn_kernel(const float* __restrict__ x, const float* __restrict__ W,
           float* __restrict__ out) {
    extern __shared__ unsigned char sm[];
    uint2*    keys = (uint2*)(sm + SM_KEYS);
    float*    LUT  = (float*)(sm + SM_LUT);
    uint32_t* xth  = (uint32_t*)(sm + SM_XTH);

    const int tid  = threadIdx.x;
    const int warp = tid >> 5;
    const int lane = tid & 31;
    const int b    = blockIdx.x * 8 + warp;      // 2048 * 8 = 16384 batches
    const uint32_t base = (uint32_t)b * NPIX;
    const uint32_t one  = (base >> 24) | 1u;     // == 1, opaque to compiler

    // --- per-timestep keys: split(key(42),100) partitionable/foldlike ---
    if (tid < T_STEPS) {
        uint32_t rk2 = 0u ^ 42u ^ 0x1BD11BDAu;
        keys[tid] = tf2x32(0u, 42u, rk2, (uint32_t)tid, one);
    }

    // --- pair subset-sum LUT: LUT[g*41 + m*10 + o] = (m&1)*W[o][2g] + (m&2)*W[o][2g+1] ---
    for (int i = tid; i < NPAIR * 4 * NOUT; i += 256) {
        int g = i / 40;
        int r = i - g * 40;
        int m = r / 10, o = r - m * 10;
        float s = 0.0f;
        if (m & 1) s += W[o * NPIX + 2 * g];
        if (m & 2) s += W[o * NPIX + 2 * g + 1];
        LUT[g * LSTR + m * 10 + o] = s;
    }

    // --- integer thresholds: u < x  <=>  ((bits1^bits2)>>9) < ceil(x * 2^23) ---
    {
        uint32_t* th = xth + warp * NPIX;
        for (int p = lane; p < NPIX; p += 32) {
            double d = (double)x[(size_t)b * NPIX + p] * 8388608.0;
            th[p] = (uint32_t)ceil(d);
        }
    }
    __syncthreads();

    const uint2* th2 = (const uint2*)(xth + warp * NPIX);  // pair thresholds, LDS.64

    float v[NOUT], cnt[NOUT];
#pragma unroll
    for (int o = 0; o < NOUT; o++) { v[o] = 0.f; cnt[o] = 0.f; }

    for (int t = 0; t < T_STEPS; t++) {
        const uint2 kk = keys[t];
        const uint32_t k0 = kk.x, k1 = kk.y, k2 = k0 ^ k1 ^ 0x1BD11BDAu;

        float acc[NOUT];
#pragma unroll
        for (int o = 0; o < NOUT; o++) acc[o] = 0.f;

        // 392 pairs = 12 full warp-iters + tail of 8 (lanes 0-7)
#pragma unroll 1
        for (int j = 0; j < 12; j++) {
            const int g = lane + 32 * j;
            const uint2 th = th2[g];
            const uint32_t c = base + 2u * (uint32_t)g;
            uint2 rA = tf2x32(k0, k1, k2, c,      one);   // two independent
            uint2 rB = tf2x32(k0, k1, k2, c + 1u, one);   // chains -> ILP x2
            uint32_t m = ((((rA.x ^ rA.y) >> 9) < th.x) ? 1u : 0u)
                       | ((((rB.x ^ rB.y) >> 9) < th.y) ? 2u : 0u);
            const float* lp = LUT + g * LSTR + m * 10;
#pragma unroll
            for (int o = 0; o < NOUT; o++) acc[o] += lp[o];
        }
        if (lane < 8) {
            const int g = 384 + lane;
            const uint2 th = th2[g];
            const uint32_t c = base + 2u * (uint32_t)g;
            uint2 rA = tf2x32(k0, k1, k2, c,      one);
            uint2 rB = tf2x32(k0, k1, k2, c + 1u, one);
            uint32_t m = ((((rA.x ^ rA.y) >> 9) < th.x) ? 1u : 0u)
                       | ((((rB.x ^ rB.y) >> 9) < th.y) ? 2u : 0u);
            const float* lp = LUT + g * LSTR + m * 10;
#pragma unroll
            for (int o = 0; o < NOUT; o++) acc[o] += lp[o];
        }

        // butterfly reduce (every lane gets totals)
#pragma unroll
        for (int off = 16; off > 0; off >>= 1) {
#pragma unroll
            for (int o = 0; o < NOUT; o++)
                acc[o] += __shfl_xor_sync(0xFFFFFFFFu, acc[o], off);
        }

        // LIF: v += (I - v)/2 ; spike if v>=1 ; hard reset (bit-exact vs XLA)
#pragma unroll
        for (int o = 0; o < NOUT; o++) {
            float nv = fmaf(acc[o] - v[o], 0.5f, v[o]);
            if (nv >= 1.0f) { cnt[o] += 1.0f; nv = 0.0f; }
            v[o] = nv;
        }
    }

    if (lane == 0) {
#pragma unroll
        for (int o = 0; o < NOUT; o++)
            out[(size_t)b * NOUT + o] = cnt[o] / 100.0f;
    }
}

extern "C" void kernel_launch(void* const* d_in, const int* in_sizes, int n_in,
                              void* d_out, int out_size) {
    const float* x = (const float*)d_in[0];   // [16384,1,28,28] f32
    const float* W = (const float*)d_in[1];   // [10,784] f32
    float* out = (float*)d_out;               // [16384,10] f32

    cudaFuncSetAttribute(snn_kernel, cudaFuncAttributeMaxDynamicSharedMemorySize,
                         SM_TOTAL);
    snn_kernel<<<2048, 256, SM_TOTAL>>>(x, W, out);
}

// round 4
// speedup vs baseline: 1.1140x; 1.0008x over previous
#include <cuda_runtime.h>
#include <cstdint>
#include <math.h>

#define T_STEPS 100
#define NPIX    784
#define NPAIR   392
#define NOUT    10
#define LSTR    41           /* LUT stride words: 4 patterns * 10 + 1 pad (conflict-free) */
#define WARPS_PB 28
#define THREADS  (WARPS_PB * 32)
#define NBATCH   16384

// Integer add forced onto the FMA pipe (IMAD): d = a*one + b, one==1 at runtime
// but opaque to the compiler so it cannot strength-reduce to IADD3.
__device__ __forceinline__ uint32_t madd(uint32_t a, uint32_t b, uint32_t one) {
    uint32_t d;
    asm("mad.lo.u32 %0, %1, %2, %3;" : "=r"(d) : "r"(a), "r"(one), "r"(b));
    return d;
}

// JAX threefry2x32, exact; x0 initial = 0. Adds on IMAD (fma pipe),
// rot/xor on the ALU pipe -> balanced dual-pipe utilization.
__device__ __forceinline__ uint2 tf2x32(uint32_t k0, uint32_t k1, uint32_t k2,
                                        uint32_t x1in, uint32_t one) {
    uint32_t x0 = k0;                       // 0 + k0
    uint32_t x1 = madd(x1in, k1, one);
#define R(r) { x0 = madd(x0, x1, one); x1 = __funnelshift_l(x1, x1, (r)); x1 ^= x0; }
    R(13) R(15) R(26) R(6)
    x0 = madd(x0, k1, one); x1 = madd(x1, k2 + 1u, one);
    R(17) R(29) R(16) R(24)
    x0 = madd(x0, k2, one); x1 = madd(x1, k0 + 2u, one);
    R(13) R(15) R(26) R(6)
    x0 = madd(x0, k0, one); x1 = madd(x1, k1 + 3u, one);
    R(17) R(29) R(16) R(24)
    x0 = madd(x0, k1, one); x1 = madd(x1, k2 + 4u, one);
    R(13) R(15) R(26) R(6)
    x0 = madd(x0, k2, one); x1 = madd(x1, k0 + 5u, one);
#undef R
    return make_uint2(x0, x1);
}

// smem: keys (800B) | pair-LUT (392*41*4 = 64288B) | xth (28*784*4 = 87808B)
#define SM_KEYS  0
#define SM_LUT   800
#define SM_XTH   (SM_LUT + NPAIR * LSTR * 4)
#define SM_TOTAL (SM_XTH + WARPS_PB * NPIX * 4)

__global__ void __launch_bounds__(THREADS, 1)
snn_kernel(const float* __restrict__ x, const float* __restrict__ W,
           float* __restrict__ out) {
    extern __shared__ unsigned char sm[];
    uint2*    keys = (uint2*)(sm + SM_KEYS);
    float*    LUT  = (float*)(sm + SM_LUT);
    uint32_t* xth  = (uint32_t*)(sm + SM_XTH);

    const int tid  = threadIdx.x;
    const int warp = tid >> 5;
    const int lane = tid & 31;
    const int b    = blockIdx.x * WARPS_PB + warp;
    const bool active = (b < NBATCH);
    const uint32_t base = active ? (uint32_t)b * NPIX : 0u;
    const uint32_t one  = (base >> 24) | 1u;     // == 1, opaque to compiler

    // --- per-timestep keys: split(key(42),100) partitionable/foldlike ---
    if (tid < T_STEPS) {
        uint32_t rk2 = 0u ^ 42u ^ 0x1BD11BDAu;
        keys[tid] = tf2x32(0u, 42u, rk2, (uint32_t)tid, one);
    }

    // --- pair subset-sum LUT: LUT[g*41 + m*10 + o] ---
    for (int i = tid; i < NPAIR * 4 * NOUT; i += THREADS) {
        int g = i / 40;
        int r = i - g * 40;
        int m = r / 10, o = r - m * 10;
        float s = 0.0f;
        if (m & 1) s += W[o * NPIX + 2 * g];
        if (m & 2) s += W[o * NPIX + 2 * g + 1];
        LUT[g * LSTR + m * 10 + o] = s;
    }

    // --- pre-shifted saturated thresholds:
    //     spike <=> (bits>>9) < t  <=>  bits < (t<<9), sat at t = 2^23 ---
    if (active) {
        uint32_t* th = xth + warp * NPIX;
        for (int p = lane; p < NPIX; p += 32) {
            double d = (double)x[(size_t)b * NPIX + p] * 8388608.0;
            uint32_t t = (uint32_t)ceil(d);
            th[p] = (t >= 8388608u) ? 0xFFFFFFFFu : (t << 9);
        }
    }
    __syncthreads();
    if (!active) return;

    const uint2* th2 = (const uint2*)(xth + warp * NPIX);  // pair thresholds, LDS.64

    float v[NOUT], cnt[NOUT];
#pragma unroll
    for (int o = 0; o < NOUT; o++) { v[o] = 0.f; cnt[o] = 0.f; }

    for (int t = 0; t < T_STEPS; t++) {
        const uint2 kk = keys[t];
        const uint32_t k0 = kk.x, k1 = kk.y, k2 = k0 ^ k1 ^ 0x1BD11BDAu;

        float acc[NOUT];
#pragma unroll
        for (int o = 0; o < NOUT; o++) acc[o] = 0.f;

        // 392 pairs = 12 full warp-iters + tail of 8 (lanes 0-7)
#pragma unroll 1
        for (int j = 0; j < 12; j++) {
            const int g = lane + 32 * j;
            const uint2 th = th2[g];
            const uint32_t c = base + 2u * (uint32_t)g;
            uint2 rA = tf2x32(k0, k1, k2, c,      one);   // two independent
            uint2 rB = tf2x32(k0, k1, k2, c + 1u, one);   // chains -> ILP x2
            uint32_t m = (((rA.x ^ rA.y) < th.x) ? 1u : 0u)
                       | (((rB.x ^ rB.y) < th.y) ? 2u : 0u);
            const float* lp = LUT + g * LSTR + m * 10;
#pragma unroll
            for (int o = 0; o < NOUT; o++) acc[o] += lp[o];
        }
        if (lane < 8) {
            const int g = 384 + lane;
            const uint2 th = th2[g];
            const uint32_t c = base + 2u * (uint32_t)g;
            uint2 rA = tf2x32(k0, k1, k2, c,      one);
            uint2 rB = tf2x32(k0, k1, k2, c + 1u, one);
            uint32_t m = (((rA.x ^ rA.y) < th.x) ? 1u : 0u)
                       | (((rB.x ^ rB.y) < th.y) ? 2u : 0u);
            const float* lp = LUT + g * LSTR + m * 10;
#pragma unroll
            for (int o = 0; o < NOUT; o++) acc[o] += lp[o];
        }

        // butterfly reduce (every lane gets totals)
#pragma unroll
        for (int off = 16; off > 0; off >>= 1) {
#pragma unroll
            for (int o = 0; o < NOUT; o++)
                acc[o] += __shfl_xor_sync(0xFFFFFFFFu, acc[o], off);
        }

        // LIF: v += (I - v)/2 ; spike if v>=1 ; hard reset (bit-exact vs XLA)
#pragma unroll
        for (int o = 0; o < NOUT; o++) {
            float nv = fmaf(acc[o] - v[o], 0.5f, v[o]);
            if (nv >= 1.0f) { cnt[o] += 1.0f; nv = 0.0f; }
            v[o] = nv;
        }
    }

    if (lane == 0) {
#pragma unroll
        for (int o = 0; o < NOUT; o++)
            out[(size_t)b * NOUT + o] = cnt[o] / 100.0f;
    }
}

extern "C" void kernel_launch(void* const* d_in, const int* in_sizes, int n_in,
                              void* d_out, int out_size) {
    const float* x = (const float*)d_in[0];   // [16384,1,28,28] f32
    const float* W = (const float*)d_in[1];   // [10,784] f32
    float* out = (float*)d_out;               // [16384,10] f32

    const int nblocks = (NBATCH + WARPS_PB - 1) / WARPS_PB;   // 586
    cudaFuncSetAttribute(snn_kernel, cudaFuncAttributeMaxDynamicSharedMemorySize,
                         SM_TOTAL);
    snn_kernel<<<nblocks, THREADS, SM_TOTAL>>>(x, W, out);
}

// round 6
// speedup vs baseline: 1.1608x; 1.0420x over previous
#include <cuda_runtime.h>
#include <cstdint>
#include <math.h>

#define T_STEPS 100
#define NPIX    784
#define NPAIR   392
#define NOUT    10
#define LSTR    42           /* LUT stride words: 4*10 + 2 pad; 8B-aligned, dword-bank clean */
#define WARPS_PB 28
#define THREADS  (WARPS_PB * 32)
#define NBATCH   16384

// Integer add forced onto the FMA pipe (IMAD): d = a*one + b, one==1 at runtime
// but opaque to the compiler so it cannot strength-reduce to IADD3.
__device__ __forceinline__ uint32_t madd(uint32_t a, uint32_t b, uint32_t one) {
    uint32_t d;
    asm("mad.lo.u32 %0, %1, %2, %3;" : "=r"(d) : "r"(a), "r"(one), "r"(b));
    return d;
}

// JAX threefry2x32, exact; x0 initial = 0. Adds on IMAD (fma pipe),
// rot/xor on the ALU pipe -> balanced dual-pipe utilization.
__device__ __forceinline__ uint2 tf2x32(uint32_t k0, uint32_t k1, uint32_t k2,
                                        uint32_t x1in, uint32_t one) {
    uint32_t x0 = k0;                       // 0 + k0
    uint32_t x1 = madd(x1in, k1, one);
#define R(r) { x0 = madd(x0, x1, one); x1 = __funnelshift_l(x1, x1, (r)); x1 ^= x0; }
    R(13) R(15) R(26) R(6)
    x0 = madd(x0, k1, one); x1 = madd(x1, k2 + 1u, one);
    R(17) R(29) R(16) R(24)
    x0 = madd(x0, k2, one); x1 = madd(x1, k0 + 2u, one);
    R(13) R(15) R(26) R(6)
    x0 = madd(x0, k0, one); x1 = madd(x1, k1 + 3u, one);
    R(17) R(29) R(16) R(24)
    x0 = madd(x0, k1, one); x1 = madd(x1, k2 + 4u, one);
    R(13) R(15) R(26) R(6)
    x0 = madd(x0, k2, one); x1 = madd(x1, k0 + 5u, one);
#undef R
    return make_uint2(x0, x1);
}

__device__ __forceinline__ uint32_t smem_u32(const void* p) {
    uint32_t a;
    asm("{ .reg .u64 t; cvta.to.shared.u64 t, %1; cvt.u32.u64 %0, t; }"
        : "=r"(a) : "l"(p));
    return a;
}

// smem: keys (800B) | pair-LUT (392*42*4 = 65856B) | xth (28*784*4 = 87808B)
//       | 256B guard pad (last warp's j=11 threshold prefetch over-reads up to
//         th_base + 3072 + 248 + 8 bytes; pad keeps it inside the allocation)
#define SM_KEYS  0
#define SM_LUT   800
#define SM_XTH   (SM_LUT + NPAIR * LSTR * 4)
#define SM_TOTAL (SM_XTH + WARPS_PB * NPIX * 4 + 256)

__global__ void __launch_bounds__(THREADS, 1)
snn_kernel(const float* __restrict__ x, const float* __restrict__ W,
           float* __restrict__ out) {
    extern __shared__ unsigned char sm[];
    uint2*    keys = (uint2*)(sm + SM_KEYS);
    float*    LUT  = (float*)(sm + SM_LUT);
    uint32_t* xth  = (uint32_t*)(sm + SM_XTH);

    const int tid  = threadIdx.x;
    const int warp = tid >> 5;
    const int lane = tid & 31;
    const int b    = blockIdx.x * WARPS_PB + warp;
    const bool active = (b < NBATCH);
    const uint32_t base = active ? (uint32_t)b * NPIX : 0u;
    const uint32_t one  = (base >> 24) | 1u;     // == 1, opaque to compiler

    // --- per-timestep keys: split(key(42),100) partitionable/foldlike ---
    if (tid < T_STEPS) {
        uint32_t rk2 = 0u ^ 42u ^ 0x1BD11BDAu;
        keys[tid] = tf2x32(0u, 42u, rk2, (uint32_t)tid, one);
    }

    // --- pair subset-sum LUT: LUT[g*42 + m*10 + o] ---
    for (int i = tid; i < NPAIR * 4 * NOUT; i += THREADS) {
        int g = i / 40;
        int r = i - g * 40;
        int m = r / 10, o = r - m * 10;
        float s = 0.0f;
        if (m & 1) s += W[o * NPIX + 2 * g];
        if (m & 2) s += W[o * NPIX + 2 * g + 1];
        LUT[g * LSTR + m * 10 + o] = s;
    }

    // --- pre-shifted saturated thresholds:
    //     spike <=> (bits>>9) < t  <=>  bits < (t<<9), sat at t = 2^23 ---
    if (active) {
        uint32_t* th = xth + warp * NPIX;
        for (int p = lane; p < NPIX; p += 32) {
            double d = (double)x[(size_t)b * NPIX + p] * 8388608.0;
            uint32_t t = (uint32_t)ceil(d);
            th[p] = (t >= 8388608u) ? 0xFFFFFFFFu : (t << 9);
        }
    }
    __syncthreads();
    if (!active) return;

    const uint32_t lut_s  = smem_u32(LUT);
    const uint32_t th_s0  = smem_u32(xth + warp * NPIX) + (uint32_t)lane * 8u;
    const uint32_t lut_l0 = lut_s + (uint32_t)lane * (LSTR * 4);

    float v[NOUT], cnt[NOUT];
#pragma unroll
    for (int o = 0; o < NOUT; o++) { v[o] = 0.f; cnt[o] = 0.f; }

    for (int t = 0; t < T_STEPS; t++) {
        const uint2 kk = keys[t];
        const uint32_t k0 = kk.x, k1 = kk.y, k2 = k0 ^ k1 ^ 0x1BD11BDAu;

        unsigned long long acc2[5];
#pragma unroll
        for (int k = 0; k < 5; k++) acc2[k] = 0ULL;

        // running state (advanced on fma pipe)
        uint32_t c      = base + 2u * (uint32_t)lane;  // counter for pixel 2g
        uint32_t th_ptr = th_s0;
        uint32_t lut_g  = lut_l0;

        uint2 th;
        asm("ld.shared.v2.u32 {%0,%1}, [%2];" : "=r"(th.x), "=r"(th.y) : "r"(th_ptr));

        // 392 pairs = 12 full warp-iters + tail of 8 (lanes 0-7)
#pragma unroll 1
        for (int j = 0; j < 12; j++) {
            uint2 rA = tf2x32(k0, k1, k2, c,      one);   // two independent
            uint2 rB = tf2x32(k0, k1, k2, c + 1u, one);   // chains -> ILP x2

            // prefetch next iteration's thresholds (latency hidden by hashes);
            // j=11 fetch supplies the tail's pairs (lanes 0-7), covered by pad
            uint2 thn;
            asm("ld.shared.v2.u32 {%0,%1}, [%2+256];" : "=r"(thn.x), "=r"(thn.y) : "r"(th_ptr));

            uint32_t m = (((rA.x ^ rA.y) < th.x) ? 40u : 0u)
                       | (((rB.x ^ rB.y) < th.y) ? 80u : 0u);
            uint32_t lp = madd(m, lut_g, one);            // byte addr of LUT row
#pragma unroll
            for (int k = 0; k < 5; k++) {
                unsigned long long w;
                asm("ld.shared.b64 %0, [%1];" : "=l"(w) : "r"(lp + 8u * k));
                asm("add.rn.f32x2 %0, %1, %2;" : "=l"(acc2[k]) : "l"(acc2[k]), "l"(w));
            }

            th = thn;
            c      = madd(c, 64u, one);
            th_ptr = madd(th_ptr, 256u, one);
            lut_g  = madd(lut_g, 32u * LSTR * 4u, one);
        }
        if (lane < 8) {
            uint2 rA = tf2x32(k0, k1, k2, c,      one);
            uint2 rB = tf2x32(k0, k1, k2, c + 1u, one);
            uint32_t m = (((rA.x ^ rA.y) < th.x) ? 40u : 0u)
                       | (((rB.x ^ rB.y) < th.y) ? 80u : 0u);
            uint32_t lp = madd(m, lut_g, one);
#pragma unroll
            for (int k = 0; k < 5; k++) {
                unsigned long long w;
                asm("ld.shared.b64 %0, [%1];" : "=l"(w) : "r"(lp + 8u * k));
                asm("add.rn.f32x2 %0, %1, %2;" : "=l"(acc2[k]) : "l"(acc2[k]), "l"(w));
            }
        }

        // unpack and butterfly reduce (every lane gets totals)
        float acc[NOUT];
#pragma unroll
        for (int k = 0; k < 5; k++)
            asm("mov.b64 {%0, %1}, %2;" : "=f"(acc[2 * k]), "=f"(acc[2 * k + 1]) : "l"(acc2[k]));
#pragma unroll
        for (int off = 16; off > 0; off >>= 1) {
#pragma unroll
            for (int o = 0; o < NOUT; o++)
                acc[o] += __shfl_xor_sync(0xFFFFFFFFu, acc[o], off);
        }

        // LIF: v += (I - v)/2 ; spike if v>=1 ; hard reset (bit-exact vs XLA)
#pragma unroll
        for (int o = 0; o < NOUT; o++) {
            float nv = fmaf(acc[o] - v[o], 0.5f, v[o]);
            if (nv >= 1.0f) { cnt[o] += 1.0f; nv = 0.0f; }
            v[o] = nv;
        }
    }

    if (lane == 0) {
#pragma unroll
        for (int o = 0; o < NOUT; o++)
            out[(size_t)b * NOUT + o] = cnt[o] / 100.0f;
    }
}

extern "C" void kernel_launch(void* const* d_in, const int* in_sizes, int n_in,
                              void* d_out, int out_size) {
    const float* x = (const float*)d_in[0];   // [16384,1,28,28] f32
    const float* W = (const float*)d_in[1];   // [10,784] f32
    float* out = (float*)d_out;               // [16384,10] f32

    const int nblocks = (NBATCH + WARPS_PB - 1) / WARPS_PB;   // 586
    cudaFuncSetAttribute(snn_kernel, cudaFuncAttributeMaxDynamicSharedMemorySize,
                         SM_TOTAL);
    snn_kernel<<<nblocks, THREADS, SM_TOTAL>>>(x, W, out);
}

// round 7
// speedup vs baseline: 1.2914x; 1.1124x over previous
#include <cuda_runtime.h>
#include <cstdint>
#include <math.h>

#define T_STEPS 100
#define NPIX    784
#define NPAIR   392
#define NOUT    10
#define LSTR    42           /* LUT stride words: 4*10 + 2 pad; 8B-aligned */
#define WARPS_PB 28
#define THREADS  (WARPS_PB * 32)
#define NBATCH   16384

// Integer add forced onto the FMA pipe (IMAD): d = a*one + b, one==1 at runtime
// but opaque to the compiler so it cannot strength-reduce to IADD3.
__device__ __forceinline__ uint32_t madd(uint32_t a, uint32_t b, uint32_t one) {
    uint32_t d;
    asm("mad.lo.u32 %0, %1, %2, %3;" : "=r"(d) : "r"(a), "r"(one), "r"(b));
    return d;
}

struct TFK { uint32_t k0, k1, k2, i1, i2, i3, i4, i5; };

// JAX threefry2x32, exact; x0 initial = 0; injection consts precomputed per t.
__device__ __forceinline__ uint2 tf2x32(const TFK& K, uint32_t ctr, uint32_t one) {
    uint32_t x0 = K.k0;
    uint32_t x1 = madd(ctr, K.k1, one);
#define R(r) { x0 = madd(x0, x1, one); x1 = __funnelshift_l(x1, x1, (r)); x1 ^= x0; }
    R(13) R(15) R(26) R(6)
    x0 = madd(x0, K.k1, one); x1 = madd(x1, K.i1, one);
    R(17) R(29) R(16) R(24)
    x0 = madd(x0, K.k2, one); x1 = madd(x1, K.i2, one);
    R(13) R(15) R(26) R(6)
    x0 = madd(x0, K.k0, one); x1 = madd(x1, K.i3, one);
    R(17) R(29) R(16) R(24)
    x0 = madd(x0, K.k1, one); x1 = madd(x1, K.i4, one);
    R(13) R(15) R(26) R(6)
    x0 = madd(x0, K.k2, one); x1 = madd(x1, K.i5, one);
#undef R
    return make_uint2(x0, x1);
}

__device__ __forceinline__ uint32_t smem_u32(const void* p) {
    uint32_t a;
    asm("{ .reg .u64 t; cvta.to.shared.u64 t, %1; cvt.u32.u64 %0, t; }"
        : "=r"(a) : "l"(p));
    return a;
}

// smem: keys (800B) | pair-LUT (392*42*4 = 65856B) | xth (28*784*4 = 87808B)
//       | 512B guard pad for the last warp's deepest threshold prefetch
#define SM_KEYS  0
#define SM_LUT   800
#define SM_XTH   (SM_LUT + NPAIR * LSTR * 4)
#define SM_TOTAL (SM_XTH + WARPS_PB * NPIX * 4 + 512)

__global__ void __launch_bounds__(THREADS, 1)
snn_kernel(const float* __restrict__ x, const float* __restrict__ W,
           float* __restrict__ out) {
    extern __shared__ unsigned char sm[];
    uint2*    keys = (uint2*)(sm + SM_KEYS);
    float*    LUT  = (float*)(sm + SM_LUT);
    uint32_t* xth  = (uint32_t*)(sm + SM_XTH);

    const int tid  = threadIdx.x;
    const int warp = tid >> 5;
    const int lane = tid & 31;
    const int b    = blockIdx.x * WARPS_PB + warp;
    const bool active = (b < NBATCH);
    const uint32_t base = active ? (uint32_t)b * NPIX : 0u;
    const uint32_t one  = (base >> 24) | 1u;     // == 1, opaque to compiler

    // --- per-timestep keys: split(key(42),100) partitionable/foldlike ---
    if (tid < T_STEPS) {
        TFK K0;
        K0.k0 = 0u; K0.k1 = 42u; K0.k2 = 0u ^ 42u ^ 0x1BD11BDAu;
        K0.i1 = K0.k2 + 1u; K0.i2 = K0.k0 + 2u; K0.i3 = K0.k1 + 3u;
        K0.i4 = K0.k2 + 4u; K0.i5 = K0.k0 + 5u;
        keys[tid] = tf2x32(K0, (uint32_t)tid, one);
    }

    // --- pair subset-sum LUT: LUT[g*42 + m*10 + o] ---
    for (int i = tid; i < NPAIR * 4 * NOUT; i += THREADS) {
        int g = i / 40;
        int r = i - g * 40;
        int m = r / 10, o = r - m * 10;
        float s = 0.0f;
        if (m & 1) s += W[o * NPIX + 2 * g];
        if (m & 2) s += W[o * NPIX + 2 * g + 1];
        LUT[g * LSTR + m * 10 + o] = s;
    }

    // --- pre-shifted saturated thresholds:
    //     spike <=> (bits>>9) < t  <=>  bits < (t<<9), sat at t = 2^23 ---
    if (active) {
        uint32_t* th = xth + warp * NPIX;
        for (int p = lane; p < NPIX; p += 32) {
            double d = (double)x[(size_t)b * NPIX + p] * 8388608.0;
            uint32_t t = (uint32_t)ceil(d);
            th[p] = (t >= 8388608u) ? 0xFFFFFFFFu : (t << 9);
        }
    }
    __syncthreads();
    if (!active) return;

    const uint32_t th_s0  = smem_u32(xth + warp * NPIX) + (uint32_t)lane * 8u;
    const uint32_t lut_l0 = smem_u32(LUT) + (uint32_t)lane * (LSTR * 4);

    float v[NOUT], cnt[NOUT];
#pragma unroll
    for (int o = 0; o < NOUT; o++) { v[o] = 0.f; cnt[o] = 0.f; }

    for (int t = 0; t < T_STEPS; t++) {
        const uint2 kk = keys[t];
        TFK K;
        K.k0 = kk.x; K.k1 = kk.y; K.k2 = K.k0 ^ K.k1 ^ 0x1BD11BDAu;
        K.i1 = K.k2 + 1u; K.i2 = K.k0 + 2u; K.i3 = K.k1 + 3u;
        K.i4 = K.k2 + 4u; K.i5 = K.k0 + 5u;

        unsigned long long acc2[5];
#pragma unroll
        for (int k = 0; k < 5; k++) acc2[k] = 0ULL;

        // running state (advanced on fma pipe); 2 pairs per lane per iter:
        //   pair A: g = lane + 64*j       pair B: g + 32
        uint32_t cA     = base + 2u * (uint32_t)lane;
        uint32_t th_ptr = th_s0;
        uint32_t lut_g  = lut_l0;

        uint2 thA, thB;
        asm("ld.shared.v2.u32 {%0,%1}, [%2];"     : "=r"(thA.x), "=r"(thA.y) : "r"(th_ptr));
        asm("ld.shared.v2.u32 {%0,%1}, [%2+256];" : "=r"(thB.x), "=r"(thB.y) : "r"(th_ptr));

        // 392 pairs = 6 iters * 64 pairs + tail of 8 (lanes 0-7)
#pragma unroll 1
        for (int j = 0; j < 6; j++) {
            // 4 independent hash chains -> high per-warp ILP
            uint2 rA = tf2x32(K, cA,       one);
            uint2 rB = tf2x32(K, cA + 1u,  one);
            uint2 rC = tf2x32(K, cA + 64u, one);
            uint2 rD = tf2x32(K, cA + 65u, one);

            // prefetch next iteration's thresholds (j=5 fetch feeds the tail)
            uint2 tA, tB;
            asm("ld.shared.v2.u32 {%0,%1}, [%2+512];" : "=r"(tA.x), "=r"(tA.y) : "r"(th_ptr));
            asm("ld.shared.v2.u32 {%0,%1}, [%2+768];" : "=r"(tB.x), "=r"(tB.y) : "r"(th_ptr));

            uint32_t mA = (((rA.x ^ rA.y) < thA.x) ? 40u : 0u)
                        | (((rB.x ^ rB.y) < thA.y) ? 80u : 0u);
            uint32_t mB = (((rC.x ^ rC.y) < thB.x) ? 40u : 0u)
                        | (((rD.x ^ rD.y) < thB.y) ? 80u : 0u);
            uint32_t lpA = madd(mA, lut_g, one);             // pair A LUT row
            uint32_t lpB = madd(mB, lut_g, one);             // pair B row base (-ofs)
#pragma unroll
            for (int k = 0; k < 5; k++) {
                unsigned long long wA, wB;
                asm("ld.shared.b64 %0, [%1];" : "=l"(wA) : "r"(lpA + 8u * k));
                asm("add.rn.f32x2 %0, %1, %2;" : "=l"(acc2[k]) : "l"(acc2[k]), "l"(wA));
                asm("ld.shared.b64 %0, [%1+5376];" : "=l"(wB) : "r"(lpB + 8u * k)); // +32*42*4
                asm("add.rn.f32x2 %0, %1, %2;" : "=l"(acc2[k]) : "l"(acc2[k]), "l"(wB));
            }

            thA = tA; thB = tB;
            cA     = madd(cA, 128u, one);
            th_ptr = madd(th_ptr, 512u, one);
            lut_g  = madd(lut_g, 64u * LSTR * 4u, one);
        }
        if (lane < 8) {   // tail: pair g = 384 + lane, thresholds already in thA
            uint2 rA = tf2x32(K, cA,      one);
            uint2 rB = tf2x32(K, cA + 1u, one);
            uint32_t m = (((rA.x ^ rA.y) < thA.x) ? 40u : 0u)
                       | (((rB.x ^ rB.y) < thA.y) ? 80u : 0u);
            uint32_t lp = madd(m, lut_g, one);
#pragma unroll
            for (int k = 0; k < 5; k++) {
                unsigned long long w;
                asm("ld.shared.b64 %0, [%1];" : "=l"(w) : "r"(lp + 8u * k));
                asm("add.rn.f32x2 %0, %1, %2;" : "=l"(acc2[k]) : "l"(acc2[k]), "l"(w));
            }
        }

        // unpack and butterfly reduce (every lane gets totals)
        float acc[NOUT];
#pragma unroll
        for (int k = 0; k < 5; k++)
            asm("mov.b64 {%0, %1}, %2;" : "=f"(acc[2 * k]), "=f"(acc[2 * k + 1]) : "l"(acc2[k]));
#pragma unroll
        for (int off = 16; off > 0; off >>= 1) {
#pragma unroll
            for (int o = 0; o < NOUT; o++)
                acc[o] += __shfl_xor_sync(0xFFFFFFFFu, acc[o], off);
        }

        // LIF: v += (I - v)/2 ; spike if v>=1 ; hard reset (bit-exact vs XLA)
#pragma unroll
        for (int o = 0; o < NOUT; o++) {
            float nv = fmaf(acc[o] - v[o], 0.5f, v[o]);
            if (nv >= 1.0f) { cnt[o] += 1.0f; nv = 0.0f; }
            v[o] = nv;
        }
    }

    if (lane == 0) {
#pragma unroll
        for (int o = 0; o < NOUT; o++)
            out[(size_t)b * NOUT + o] = cnt[o] / 100.0f;
    }
}

extern "C" void kernel_launch(void* const* d_in, const int* in_sizes, int n_in,
                              void* d_out, int out_size) {
    const float* x = (const float*)d_in[0];   // [16384,1,28,28] f32
    const float* W = (const float*)d_in[1];   // [10,784] f32
    float* out = (float*)d_out;               // [16384,10] f32

    const int nblocks = (NBATCH + WARPS_PB - 1) / WARPS_PB;   // 586
    cudaFuncSetAttribute(snn_kernel, cudaFuncAttributeMaxDynamicSharedMemorySize,
                         SM_TOTAL);
    snn_kernel<<<nblocks, THREADS, SM_TOTAL>>>(x, W, out);
}